// round 15
// baseline (speedup 1.0000x reference)
#include <cuda_runtime.h>
#include <cstdint>

// DeltaLoss, rank-96 factorization. R15: R7's float4-q inner loop (best measured)
// + in-block W build + fused prep + ticket finalize + 64-reg budget (occ 4) so
// the loop doesn't spill.
//  prep : blocks 0..191 -> Gti rows; blocks 192..767 -> warp-per-pair meta + zeroing.
//  lse  : PBLK=256 x QBLK=128 tiles (48KB W), lanes own 4 q (LDS.128),
//         merged-butterfly row reduce, ticket finalize. Grid 36x18=648.
// SHIFT=30 fixed-shift LSE: x<=100 -> no overflow; sums stay normal fp32.

#define NN    96
#define D     512
#define P2    4560            // NN*(NN-1)/2
#define P2PAD 4608
#define PBLK  256
#define QBLK  128
#define GQ    (P2PAD / QBLK)  // 36
#define GP    (P2PAD / PBLK)  // 18
#define NBLOCKS (GQ * GP)     // 648
#define NGRAMB 192
#define NMETAB 576
#define K2C   (-43.28085122666891f)   // -30*log2(e)
#define L2E100 144.26950408889634f    // 100*log2(e)

// ---- scratch ----
__device__ float g_gti[NN * NN];
__device__ uint32_t g_ij[P2PAD];
__device__ float g_k1[P2PAD];
__device__ float g_si[P2PAD];
__device__ float g_diag[P2PAD];
__device__ float g_rowSum[P2PAD];
__device__ float g_colSum[P2PAD];
__device__ unsigned int g_done;

__device__ __forceinline__ float ex2f(float x) {
    float y;
    asm("ex2.approx.f32 %0, %1;" : "=f"(y) : "f"(x));
    return y;
}
__device__ __forceinline__ uint32_t smem_u32(const void* p) {
    uint32_t a;
    asm("{ .reg .u64 t; cvta.to.shared.u64 t, %1; cvt.u32.u64 %0, t; }" : "=r"(a) : "l"(p));
    return a;
}
__device__ __forceinline__ float warp_sum(float v) {
    #pragma unroll
    for (int o = 16; o > 0; o >>= 1) v += __shfl_xor_sync(0xffffffffu, v, o);
    return v;
}

// ---- prep: Gti (192 blocks) + per-pair meta & zeroing (576 blocks) ----
__global__ __launch_bounds__(256) void prep_kernel(const float* __restrict__ txtf,
                                                   const float* __restrict__ imgf) {
    __shared__ float srow[D];
    const int bid = blockIdx.x;
    const int tid = threadIdx.x;
    const int w = tid >> 5, lane = tid & 31;

    if (bid < NGRAMB) {
        const int b = bid >> 1, half = bid & 1;
        if (tid < 128) ((float4*)srow)[tid] = ((const float4*)(txtf + b * D))[tid];
        __syncthreads();
        #pragma unroll
        for (int k = 0; k < 6; ++k) {
            const int r = half * 48 + w * 6 + k;
            const float4* __restrict__ vec = (const float4*)(imgf + r * D);
            float s0 = 0.f, s1 = 0.f;
            #pragma unroll
            for (int e = 0; e < 4; e += 2) {
                const float4 a0 = ((const float4*)srow)[lane + e * 32];
                const float4 g0 = vec[lane + e * 32];
                const float4 a1 = ((const float4*)srow)[lane + (e + 1) * 32];
                const float4 g1 = vec[lane + (e + 1) * 32];
                s0 = fmaf(a0.x, g0.x, s0); s0 = fmaf(a0.y, g0.y, s0);
                s0 = fmaf(a0.z, g0.z, s0); s0 = fmaf(a0.w, g0.w, s0);
                s1 = fmaf(a1.x, g1.x, s1); s1 = fmaf(a1.y, g1.y, s1);
                s1 = fmaf(a1.z, g1.z, s1); s1 = fmaf(a1.w, g1.w, s1);
            }
            const float s = warp_sum(s0 + s1);
            if (lane == 0) g_gti[b * NN + r] = s;
        }
        return;
    }

    const int m = bid - NGRAMB;
    if (tid < 8)              g_rowSum[m * 8 + tid] = 0.f;
    else if (tid < 16)        g_colSum[m * 8 + tid - 8] = 0.f;
    else if (tid == 16 && m == 0) g_done = 0u;

    const int p = m * 8 + w;
    if (p >= P2) {
        if (p < P2PAD && lane == 0) {
            g_ij[p] = 0u; g_k1[p] = 0.f; g_si[p] = 0.f; g_diag[p] = 0.f;
        }
        return;
    }

    const float disc = (2.f * NN - 1.f) * (2.f * NN - 1.f) - 8.f * (float)p;
    int i = (int)(((2.f * NN - 1.f) - sqrtf(disc)) * 0.5f);
    i = i < 0 ? 0 : (i > NN - 2 ? NN - 2 : i);
    while (i > 0 && p < i * (191 - i) / 2) --i;
    while (p >= (i + 1) * (190 - i) / 2) ++i;
    const int j = i + 1 + (p - i * (191 - i) / 2);

    const float4* __restrict__ ti = (const float4*)(txtf + i * D);
    const float4* __restrict__ tj = (const float4*)(txtf + j * D);
    const float4* __restrict__ ui = (const float4*)(imgf + i * D);
    const float4* __restrict__ uj = (const float4*)(imgf + j * D);
    float ntt = 0.f, nii = 0.f, dd = 0.f;
    #pragma unroll
    for (int e = 0; e < 4; ++e) {
        const float4 a = ti[lane + e * 32], b4 = tj[lane + e * 32];
        const float4 c = ui[lane + e * 32], d4 = uj[lane + e * 32];
        const float t0 = a.x - b4.x, t1 = a.y - b4.y, t2 = a.z - b4.z, t3 = a.w - b4.w;
        const float u0 = c.x - d4.x, u1 = c.y - d4.y, u2 = c.z - d4.z, u3 = c.w - d4.w;
        ntt = fmaf(t0, t0, ntt); ntt = fmaf(t1, t1, ntt);
        ntt = fmaf(t2, t2, ntt); ntt = fmaf(t3, t3, ntt);
        nii = fmaf(u0, u0, nii); nii = fmaf(u1, u1, nii);
        nii = fmaf(u2, u2, nii); nii = fmaf(u3, u3, nii);
        dd  = fmaf(t0, u0, dd);  dd  = fmaf(t1, u1, dd);
        dd  = fmaf(t2, u2, dd);  dd  = fmaf(t3, u3, dd);
    }
    ntt = warp_sum(ntt); nii = warp_sum(nii); dd = warp_sum(dd);
    if (lane == 0) {
        const float st = 1.f / (sqrtf(ntt) + 1e-8f);
        const float si = 1.f / (sqrtf(nii) + 1e-8f);
        g_ij[p] = (uint32_t)i | ((uint32_t)j << 8);
        g_k1[p] = L2E100 * st;
        g_si[p] = si;
        g_diag[p] = 100.f * st * si * dd;
    }
}

// one group of 4 p (lanes own 4 q each via LDS.128): compute entries,
// butterfly-reduce rows, update col accumulators
template <bool MASKED>
__device__ __forceinline__ void lse_group(
    int g, int pbase, int p0, int lane, uint32_t wbase,
    const float2* __restrict__ ksm, const uint32_t* __restrict__ offsm,
    float mq0, float mq1, float mq2, float mq3,
    float& c0, float& c1, float& c2, float& c3)
{
    float rsv[4];
    #pragma unroll
    for (int u = 0; u < 4; ++u) {
        const int p = pbase + g * 4 + u;
        const uint32_t off = offsm[p];
        const float2 kb = ksm[p];
        float4 vi, vj;
        asm volatile("ld.shared.v4.f32 {%0,%1,%2,%3}, [%4];"
            : "=f"(vi.x), "=f"(vi.y), "=f"(vi.z), "=f"(vi.w)
            : "r"(wbase + (off & 0xFFFFu)));
        asm volatile("ld.shared.v4.f32 {%0,%1,%2,%3}, [%4];"
            : "=f"(vj.x), "=f"(vj.y), "=f"(vj.z), "=f"(vj.w)
            : "r"(wbase + (off >> 16)));
        const float d0 = vi.x - vj.x, d1 = vi.y - vj.y;
        const float d2 = vi.z - vj.z, d3 = vi.w - vj.w;
        const float e0 = ex2f(fmaf(d0, kb.x, kb.y)) + ex2f(fmaf(d0, -kb.x, kb.y));
        const float e1 = ex2f(fmaf(d1, kb.x, kb.y)) + ex2f(fmaf(d1, -kb.x, kb.y));
        const float e2 = ex2f(fmaf(d2, kb.x, kb.y)) + ex2f(fmaf(d2, -kb.x, kb.y));
        const float e3 = ex2f(fmaf(d3, kb.x, kb.y)) + ex2f(fmaf(d3, -kb.x, kb.y));
        c0 += e0; c1 += e1; c2 += e2; c3 += e3;
        if constexpr (MASKED) {
            float rs = e0 * mq0;
            rs = fmaf(e1, mq1, rs);
            rs = fmaf(e2, mq2, rs);
            rs = fmaf(e3, mq3, rs);
            rsv[u] = rs;
        } else {
            rsv[u] = (e0 + e1) + (e2 + e3);
        }
    }
    // merged 4-way butterfly: lane-group (bit4, bit3) holds row sum of
    // p = pbase + g*4 + idx, idx = bit4 | (bit3 << 1)
    float v0 = rsv[0] + __shfl_xor_sync(0xffffffffu, rsv[0], 16);
    float t1 = rsv[1] + __shfl_xor_sync(0xffffffffu, rsv[1], 16);
    v0 = (lane & 16) ? t1 : v0;
    float v1 = rsv[2] + __shfl_xor_sync(0xffffffffu, rsv[2], 16);
    float t3 = rsv[3] + __shfl_xor_sync(0xffffffffu, rsv[3], 16);
    v1 = (lane & 16) ? t3 : v1;
    float u0 = v0 + __shfl_xor_sync(0xffffffffu, v0, 8);
    float u1 = v1 + __shfl_xor_sync(0xffffffffu, v1, 8);
    u0 = (lane & 8) ? u1 : u0;
    u0 += __shfl_xor_sync(0xffffffffu, u0, 4);
    u0 += __shfl_xor_sync(0xffffffffu, u0, 2);
    u0 += __shfl_xor_sync(0xffffffffu, u0, 1);
    if ((lane & 7) == 0) {
        const int idx = ((lane >> 4) & 1) | ((lane >> 2) & 2);
        atomicAdd(&g_rowSum[p0 + pbase + g * 4 + idx], u0);
    }
}

// ---- main: 48KB W tile, 256p x 128q per block, fused LSE, ticket finalize ----
__global__ void __launch_bounds__(256, 4) lse_main(float* __restrict__ out) {
    __shared__ float Wsm[NN * QBLK];                   // 49152 B
    __shared__ float2 ksm[PBLK];                       // (k1, base)
    __shared__ uint32_t offsm[PBLK];                   // packed byte offsets
    __shared__ float red[8];
    __shared__ unsigned int s_last;

    const int tid = threadIdx.x;
    const int q0 = blockIdx.x * QBLK;
    const int p0 = blockIdx.y * PBLK;

    // --- build W tile: Wsm[r][q] = si_q * (Gti[r][i_q] - Gti[r][j_q]) ---
    {
        const int q = tid & 127;
        const int half = tid >> 7;                     // r in [half*48, half*48+48)
        const uint32_t ij = g_ij[q0 + q];
        const float si = g_si[q0 + q];
        const int iq = (int)(ij & 255u), jq = (int)(ij >> 8);
        const float* __restrict__ gi = g_gti + half * 48 * NN;
        #pragma unroll 8
        for (int k = 0; k < 48; ++k) {
            const float a = __ldg(gi + k * NN + iq);
            const float b = __ldg(gi + k * NN + jq);
            Wsm[(half * 48 + k) * QBLK + q] = si * (a - b);
        }
        // per-p metadata
        const int p = p0 + tid;
        ksm[tid] = make_float2(g_k1[p], (p < P2) ? K2C : -2000.f);
        const uint32_t pij = g_ij[p];
        offsm[tid] = ((pij & 255u) * (QBLK * 4)) | (((pij >> 8) * (QBLK * 4)) << 16);
    }
    __syncthreads();

    const int w = tid >> 5, lane = tid & 31;
    const uint32_t wbase = smem_u32(Wsm) + (uint32_t)lane * 16u;
    const int pbase = w * 32;                          // 32 p per warp
    float c0 = 0.f, c1 = 0.f, c2 = 0.f, c3 = 0.f;
    const int gq = q0 + 4 * lane;

    if (q0 + QBLK <= P2) {
        #pragma unroll 2
        for (int g = 0; g < 8; ++g)
            lse_group<false>(g, pbase, p0, lane, wbase, ksm, offsm,
                             1.f, 1.f, 1.f, 1.f, c0, c1, c2, c3);
    } else {
        const float mq0 = (gq + 0 < P2) ? 1.f : 0.f;
        const float mq1 = (gq + 1 < P2) ? 1.f : 0.f;
        const float mq2 = (gq + 2 < P2) ? 1.f : 0.f;
        const float mq3 = (gq + 3 < P2) ? 1.f : 0.f;
        #pragma unroll 2
        for (int g = 0; g < 8; ++g)
            lse_group<true>(g, pbase, p0, lane, wbase, ksm, offsm,
                            mq0, mq1, mq2, mq3, c0, c1, c2, c3);
    }

    atomicAdd(&g_colSum[gq + 0], c0);
    atomicAdd(&g_colSum[gq + 1], c1);
    atomicAdd(&g_colSum[gq + 2], c2);
    atomicAdd(&g_colSum[gq + 3], c3);

    // --- last-block finalize (ticket) ---
    __syncthreads();
    if (tid == 0) {
        __threadfence();
        s_last = (atomicAdd(&g_done, 1u) == (unsigned)(NBLOCKS - 1)) ? 1u : 0u;
    }
    __syncthreads();
    if (s_last) {
        __threadfence();
        float s = 0.f;
        for (int p = tid; p < P2; p += 256)
            s += 30.0f + 0.5f * (logf(g_rowSum[p]) + logf(g_colSum[p])) - g_diag[p];
        s = warp_sum(s);
        if ((tid & 31) == 0) red[tid >> 5] = s;
        __syncthreads();
        if (tid == 0) {
            float tot = 0.f;
            #pragma unroll
            for (int k = 0; k < 8; ++k) tot += red[k];
            out[0] = tot / (float)P2;
        }
    }
}

extern "C" void kernel_launch(void* const* d_in, const int* in_sizes, int n_in,
                              void* d_out, int out_size) {
    const float* txtf = (const float*)d_in[0];
    const float* imgf = (const float*)d_in[1];
    (void)in_sizes; (void)n_in; (void)out_size;
    float* out = (float*)d_out;

    prep_kernel<<<NGRAMB + NMETAB, 256>>>(txtf, imgf);
    lse_main<<<dim3(GQ, GP), 256>>>(out);
}

// round 16
// speedup vs baseline: 1.0943x; 1.0943x over previous
#include <cuda_runtime.h>
#include <cstdint>

// DeltaLoss, rank-96 factorization. R16: revert to measured-best components.
//  prep : fused Gti rows + warp-per-pair meta + zeroing (1 launch)
//  w    : g_W[r][q] = si_q * (Gti[r][i_q] - Gti[r][j_q])  (coalesced global)
//  lse  : R7's loop (lanes own 4 q via LDS.128, W tile loaded coalesced from g_W)
//         + merged butterfly row reduce + ticket finalize. No launch_bounds cap.
// SHIFT=30 fixed-shift LSE: x<=100 -> no overflow; sums stay normal fp32.

#define NN    96
#define D     512
#define P2    4560            // NN*(NN-1)/2
#define P2PAD 4608
#define PBLK  256
#define QBLK  128
#define GQ    (P2PAD / QBLK)  // 36
#define GP    (P2PAD / PBLK)  // 18
#define NBLOCKS (GQ * GP)     // 648
#define NGRAMB 192
#define NMETAB 576
#define K2C   (-43.28085122666891f)   // -30*log2(e)
#define L2E100 144.26950408889634f    // 100*log2(e)

// ---- scratch ----
__device__ float g_gti[NN * NN];
__device__ float g_W[(size_t)NN * P2PAD];
__device__ uint32_t g_ij[P2PAD];
__device__ float g_k1[P2PAD];
__device__ float g_si[P2PAD];
__device__ float g_diag[P2PAD];
__device__ float g_rowSum[P2PAD];
__device__ float g_colSum[P2PAD];
__device__ unsigned int g_done;

__device__ __forceinline__ float ex2f(float x) {
    float y;
    asm("ex2.approx.f32 %0, %1;" : "=f"(y) : "f"(x));
    return y;
}
__device__ __forceinline__ uint32_t smem_u32(const void* p) {
    uint32_t a;
    asm("{ .reg .u64 t; cvta.to.shared.u64 t, %1; cvt.u32.u64 %0, t; }" : "=r"(a) : "l"(p));
    return a;
}
__device__ __forceinline__ float warp_sum(float v) {
    #pragma unroll
    for (int o = 16; o > 0; o >>= 1) v += __shfl_xor_sync(0xffffffffu, v, o);
    return v;
}

// ---- prep: Gti (192 blocks) + per-pair meta & zeroing (576 blocks) ----
__global__ __launch_bounds__(256) void prep_kernel(const float* __restrict__ txtf,
                                                   const float* __restrict__ imgf) {
    __shared__ float srow[D];
    const int bid = blockIdx.x;
    const int tid = threadIdx.x;
    const int w = tid >> 5, lane = tid & 31;

    if (bid < NGRAMB) {
        const int b = bid >> 1, half = bid & 1;
        if (tid < 128) ((float4*)srow)[tid] = ((const float4*)(txtf + b * D))[tid];
        __syncthreads();
        #pragma unroll
        for (int k = 0; k < 6; ++k) {
            const int r = half * 48 + w * 6 + k;
            const float4* __restrict__ vec = (const float4*)(imgf + r * D);
            float s0 = 0.f, s1 = 0.f;
            #pragma unroll
            for (int e = 0; e < 4; e += 2) {
                const float4 a0 = ((const float4*)srow)[lane + e * 32];
                const float4 g0 = vec[lane + e * 32];
                const float4 a1 = ((const float4*)srow)[lane + (e + 1) * 32];
                const float4 g1 = vec[lane + (e + 1) * 32];
                s0 = fmaf(a0.x, g0.x, s0); s0 = fmaf(a0.y, g0.y, s0);
                s0 = fmaf(a0.z, g0.z, s0); s0 = fmaf(a0.w, g0.w, s0);
                s1 = fmaf(a1.x, g1.x, s1); s1 = fmaf(a1.y, g1.y, s1);
                s1 = fmaf(a1.z, g1.z, s1); s1 = fmaf(a1.w, g1.w, s1);
            }
            const float s = warp_sum(s0 + s1);
            if (lane == 0) g_gti[b * NN + r] = s;
        }
        return;
    }

    const int m = bid - NGRAMB;
    if (tid < 8)              g_rowSum[m * 8 + tid] = 0.f;
    else if (tid < 16)        g_colSum[m * 8 + tid - 8] = 0.f;
    else if (tid == 16 && m == 0) g_done = 0u;

    const int p = m * 8 + w;
    if (p >= P2) {
        if (p < P2PAD && lane == 0) {
            g_ij[p] = 0u; g_k1[p] = 0.f; g_si[p] = 0.f; g_diag[p] = 0.f;
        }
        return;
    }

    const float disc = (2.f * NN - 1.f) * (2.f * NN - 1.f) - 8.f * (float)p;
    int i = (int)(((2.f * NN - 1.f) - sqrtf(disc)) * 0.5f);
    i = i < 0 ? 0 : (i > NN - 2 ? NN - 2 : i);
    while (i > 0 && p < i * (191 - i) / 2) --i;
    while (p >= (i + 1) * (190 - i) / 2) ++i;
    const int j = i + 1 + (p - i * (191 - i) / 2);

    const float4* __restrict__ ti = (const float4*)(txtf + i * D);
    const float4* __restrict__ tj = (const float4*)(txtf + j * D);
    const float4* __restrict__ ui = (const float4*)(imgf + i * D);
    const float4* __restrict__ uj = (const float4*)(imgf + j * D);
    float ntt = 0.f, nii = 0.f, dd = 0.f;
    #pragma unroll
    for (int e = 0; e < 4; ++e) {
        const float4 a = ti[lane + e * 32], b4 = tj[lane + e * 32];
        const float4 c = ui[lane + e * 32], d4 = uj[lane + e * 32];
        const float t0 = a.x - b4.x, t1 = a.y - b4.y, t2 = a.z - b4.z, t3 = a.w - b4.w;
        const float u0 = c.x - d4.x, u1 = c.y - d4.y, u2 = c.z - d4.z, u3 = c.w - d4.w;
        ntt = fmaf(t0, t0, ntt); ntt = fmaf(t1, t1, ntt);
        ntt = fmaf(t2, t2, ntt); ntt = fmaf(t3, t3, ntt);
        nii = fmaf(u0, u0, nii); nii = fmaf(u1, u1, nii);
        nii = fmaf(u2, u2, nii); nii = fmaf(u3, u3, nii);
        dd  = fmaf(t0, u0, dd);  dd  = fmaf(t1, u1, dd);
        dd  = fmaf(t2, u2, dd);  dd  = fmaf(t3, u3, dd);
    }
    ntt = warp_sum(ntt); nii = warp_sum(nii); dd = warp_sum(dd);
    if (lane == 0) {
        const float st = 1.f / (sqrtf(ntt) + 1e-8f);
        const float si = 1.f / (sqrtf(nii) + 1e-8f);
        g_ij[p] = (uint32_t)i | ((uint32_t)j << 8);
        g_k1[p] = L2E100 * st;
        g_si[p] = si;
        g_diag[p] = 100.f * st * si * dd;
    }
}

// ---- W[r][q] = si_q * (Gti[r][i_q] - Gti[r][j_q]) ----
__global__ __launch_bounds__(256) void w_kernel() {
    const int q = blockIdx.x * 256 + threadIdx.x;
    const int r = blockIdx.y;
    const uint32_t ij = g_ij[q];
    const float si = g_si[q];
    const float w = si * (g_gti[r * NN + (ij & 255u)] - g_gti[r * NN + (ij >> 8)]);
    g_W[(size_t)r * P2PAD + q] = w;   // pad q: si=0 -> 0
}

// one group of 4 p (lanes own 4 q via LDS.128): entries, butterfly rows, col acc
template <bool MASKED>
__device__ __forceinline__ void lse_group(
    int g, int pbase, int p0, int lane, uint32_t wbase,
    const float2* __restrict__ ksm, const uint32_t* __restrict__ offsm,
    float mq0, float mq1, float mq2, float mq3,
    float& c0, float& c1, float& c2, float& c3)
{
    float rsv[4];
    #pragma unroll
    for (int u = 0; u < 4; ++u) {
        const int p = pbase + g * 4 + u;
        const uint32_t off = offsm[p];
        const float2 kb = ksm[p];
        float4 vi, vj;
        asm volatile("ld.shared.v4.f32 {%0,%1,%2,%3}, [%4];"
            : "=f"(vi.x), "=f"(vi.y), "=f"(vi.z), "=f"(vi.w)
            : "r"(wbase + (off & 0xFFFFu)));
        asm volatile("ld.shared.v4.f32 {%0,%1,%2,%3}, [%4];"
            : "=f"(vj.x), "=f"(vj.y), "=f"(vj.z), "=f"(vj.w)
            : "r"(wbase + (off >> 16)));
        const float d0 = vi.x - vj.x, d1 = vi.y - vj.y;
        const float d2 = vi.z - vj.z, d3 = vi.w - vj.w;
        const float e0 = ex2f(fmaf(d0, kb.x, kb.y)) + ex2f(fmaf(d0, -kb.x, kb.y));
        const float e1 = ex2f(fmaf(d1, kb.x, kb.y)) + ex2f(fmaf(d1, -kb.x, kb.y));
        const float e2 = ex2f(fmaf(d2, kb.x, kb.y)) + ex2f(fmaf(d2, -kb.x, kb.y));
        const float e3 = ex2f(fmaf(d3, kb.x, kb.y)) + ex2f(fmaf(d3, -kb.x, kb.y));
        c0 += e0; c1 += e1; c2 += e2; c3 += e3;
        if constexpr (MASKED) {
            float rs = e0 * mq0;
            rs = fmaf(e1, mq1, rs);
            rs = fmaf(e2, mq2, rs);
            rs = fmaf(e3, mq3, rs);
            rsv[u] = rs;
        } else {
            rsv[u] = (e0 + e1) + (e2 + e3);
        }
    }
    // merged 4-way butterfly: lane-group (bit4, bit3) holds row sum of
    // p = pbase + g*4 + idx, idx = bit4 | (bit3 << 1)
    float v0 = rsv[0] + __shfl_xor_sync(0xffffffffu, rsv[0], 16);
    float t1 = rsv[1] + __shfl_xor_sync(0xffffffffu, rsv[1], 16);
    v0 = (lane & 16) ? t1 : v0;
    float v1 = rsv[2] + __shfl_xor_sync(0xffffffffu, rsv[2], 16);
    float t3 = rsv[3] + __shfl_xor_sync(0xffffffffu, rsv[3], 16);
    v1 = (lane & 16) ? t3 : v1;
    float u0 = v0 + __shfl_xor_sync(0xffffffffu, v0, 8);
    float u1 = v1 + __shfl_xor_sync(0xffffffffu, v1, 8);
    u0 = (lane & 8) ? u1 : u0;
    u0 += __shfl_xor_sync(0xffffffffu, u0, 4);
    u0 += __shfl_xor_sync(0xffffffffu, u0, 2);
    u0 += __shfl_xor_sync(0xffffffffu, u0, 1);
    if ((lane & 7) == 0) {
        const int idx = ((lane >> 4) & 1) | ((lane >> 2) & 2);
        atomicAdd(&g_rowSum[p0 + pbase + g * 4 + idx], u0);
    }
}

// ---- main: W tile loaded coalesced from g_W, 256p x 128q, ticket finalize ----
__global__ void __launch_bounds__(256) lse_main(float* __restrict__ out) {
    __shared__ float Wsm[NN * QBLK];                   // 49152 B
    __shared__ float2 ksm[PBLK];                       // (k1, base)
    __shared__ uint32_t offsm[PBLK];                   // packed byte offsets
    __shared__ float red[8];
    __shared__ unsigned int s_last;

    const int tid = threadIdx.x;
    const int q0 = blockIdx.x * QBLK;
    const int p0 = blockIdx.y * PBLK;

    // stage W tile (96 x 128 floats) via float4: 3072 float4 / 256 thr = 12 each
    #pragma unroll
    for (int k = 0; k < 12; ++k) {
        const int f4 = tid + k * 256;
        const int r = f4 >> 5, c = f4 & 31;
        ((float4*)Wsm)[f4] = *(const float4*)(g_W + (size_t)r * P2PAD + q0 + c * 4);
    }
    {
        const int p = p0 + tid;
        ksm[tid] = make_float2(g_k1[p], (p < P2) ? K2C : -2000.f);
        const uint32_t pij = g_ij[p];
        offsm[tid] = ((pij & 255u) * (QBLK * 4)) | (((pij >> 8) * (QBLK * 4)) << 16);
    }
    __syncthreads();

    const int w = tid >> 5, lane = tid & 31;
    const uint32_t wbase = smem_u32(Wsm) + (uint32_t)lane * 16u;
    const int pbase = w * 32;                          // 32 p per warp
    float c0 = 0.f, c1 = 0.f, c2 = 0.f, c3 = 0.f;
    const int gq = q0 + 4 * lane;

    if (q0 + QBLK <= P2) {
        #pragma unroll 2
        for (int g = 0; g < 8; ++g)
            lse_group<false>(g, pbase, p0, lane, wbase, ksm, offsm,
                             1.f, 1.f, 1.f, 1.f, c0, c1, c2, c3);
    } else {
        const float mq0 = (gq + 0 < P2) ? 1.f : 0.f;
        const float mq1 = (gq + 1 < P2) ? 1.f : 0.f;
        const float mq2 = (gq + 2 < P2) ? 1.f : 0.f;
        const float mq3 = (gq + 3 < P2) ? 1.f : 0.f;
        #pragma unroll 2
        for (int g = 0; g < 8; ++g)
            lse_group<true>(g, pbase, p0, lane, wbase, ksm, offsm,
                            mq0, mq1, mq2, mq3, c0, c1, c2, c3);
    }

    atomicAdd(&g_colSum[gq + 0], c0);
    atomicAdd(&g_colSum[gq + 1], c1);
    atomicAdd(&g_colSum[gq + 2], c2);
    atomicAdd(&g_colSum[gq + 3], c3);

    // --- last-block finalize (ticket) ---
    __syncthreads();
    if (tid == 0) {
        __threadfence();
        s_last = (atomicAdd(&g_done, 1u) == (unsigned)(NBLOCKS - 1)) ? 1u : 0u;
    }
    __syncthreads();
    if (s_last) {
        __threadfence();
        float s = 0.f;
        for (int p = tid; p < P2; p += 256)
            s += 30.0f + 0.5f * (logf(g_rowSum[p]) + logf(g_colSum[p])) - g_diag[p];
        s = warp_sum(s);
        if ((tid & 31) == 0) red[tid >> 5] = s;
        __syncthreads();
        if (tid == 0) {
            float tot = 0.f;
            #pragma unroll
            for (int k = 0; k < 8; ++k) tot += red[k];
            out[0] = tot / (float)P2;
        }
    }
}

extern "C" void kernel_launch(void* const* d_in, const int* in_sizes, int n_in,
                              void* d_out, int out_size) {
    const float* txtf = (const float*)d_in[0];
    const float* imgf = (const float*)d_in[1];
    (void)in_sizes; (void)n_in; (void)out_size;
    float* out = (float*)d_out;

    prep_kernel<<<NGRAMB + NMETAB, 256>>>(txtf, imgf);
    w_kernel<<<dim3(P2PAD / 256, NN), 256>>>();
    lse_main<<<dim3(GQ, GP), 256>>>(out);
}